// round 11
// baseline (speedup 1.0000x reference)
#include <cuda_runtime.h>
#include <cuda_fp16.h>
#include <cstdint>

#define NCTA 128
#define OFF_STA 131072                 // after 128KB resident w
#define SMEM_MAIN (131072 + 3 * 16384) // 180224

// ---------------- device scratch ----------------
__device__ __align__(128) unsigned char g_hpack[1048576]; // [b1024][k512] fp16 h
__device__ __align__(128) unsigned char g_wpack[2097152]; // [n2048 perm][k512] fp16 w
__device__ float g_xT[512 * 1024];
__device__ float g_xdec[48 * 1024];
__device__ __align__(128) unsigned g_cnt8[256];   // 8 group counters, 128B apart

__device__ __forceinline__ float tanha(float x) {
    float r;
    asm("tanh.approx.f32 %0, %1;" : "=f"(r) : "f"(x));
    return r;
}
__device__ __forceinline__ float sigm(float x) {
    return fmaf(tanha(0.5f * x), 0.5f, 0.5f);
}
__device__ __forceinline__ void cpa16(unsigned dst, const void* src) {
    asm volatile("cp.async.cg.shared.global [%0], [%1], 16;" :: "r"(dst), "l"(src));
}
__device__ __forceinline__ void ldmx4(uint32_t& r0, uint32_t& r1, uint32_t& r2,
                                      uint32_t& r3, unsigned a) {
    asm volatile("ldmatrix.sync.aligned.m8n8.x4.shared.b16 {%0,%1,%2,%3}, [%4];"
        : "=r"(r0), "=r"(r1), "=r"(r2), "=r"(r3) : "r"(a));
}
// fp16-accumulate legacy HMMA (2x rate path on most archs)
__device__ __forceinline__ void mma16816h(uint32_t* d, const uint32_t* a,
                                          uint32_t b0, uint32_t b1) {
    asm volatile("mma.sync.aligned.m16n8k16.row.col.f16.f16.f16.f16 "
        "{%0,%1}, {%2,%3,%4,%5}, {%6,%7}, {%0,%1};"
        : "+r"(d[0]), "+r"(d[1])
        : "r"(a[0]), "r"(a[1]), "r"(a[2]), "r"(a[3]), "r"(b0), "r"(b1));
}

// ---------------- prologue kernels ----------------
extern "C" __global__ void prep_k(const float* __restrict__ x) {
    int n = blockIdx.x * 256 + threadIdx.x;          // 0..524287
    int b = n >> 9, t = n & 511;
    g_xT[t * 1024 + b] = x[n];                       // x[b][t][0]
    if (n < 262144) ((uint32_t*)g_hpack)[n] = 0u;    // zero h plane (1MB)
    if (n < 48 * 1024) g_xdec[n] = 0.f;
    if (n < 256) g_cnt8[n] = 0u;                     // reset group barriers
}

extern "C" __global__ void pack_w(const float* __restrict__ w_hh) {
    int n = blockIdx.x * 256 + threadIdx.x;          // 0..1048575
    int k = n & 511, ng = n >> 9;
    int j = ng >> 7, nl = ng & 127;
    int wn = nl >> 5, gate = (nl >> 3) & 3, ul = nl & 7;
    int row = gate * 512 + j * 32 + wn * 8 + ul;
    ((__half*)g_wpack)[ng * 512 + k] = __float2half_rn(w_hh[row * 512 + k]);
}

// ---------------- main persistent kernel ----------------
extern "C" __global__ void __launch_bounds__(256, 1)
lstm_mma(const float* __restrict__ w_ih, const float* __restrict__ b_ih,
         const float* __restrict__ b_hh, const float* __restrict__ w_fc,
         const float* __restrict__ b_fc, float* __restrict__ dout)
{
    extern __shared__ __align__(1024) char smem[];
    const unsigned sa = (unsigned)__cvta_generic_to_shared(smem);

    const int tid = threadIdx.x;
    const int lane = tid & 31, w = tid >> 5;
    const int wm = w >> 2, wn = w & 3;
    const int ql = lane & 3, qr = lane >> 2;
    const int i = blockIdx.x & 7, j = blockIdx.x >> 3;
    unsigned* const cptr = g_cnt8 + (i << 5);   // this group's barrier counter

    // per-thread constants: bias, w_ih, w_fc for its 2 units x 4 gates
    float bs[4][2], ws[4][2], wfc_r[2];
    #pragma unroll
    for (int d = 0; d < 2; ++d) {
        int u = j * 32 + wn * 8 + 2 * ql + d;
        wfc_r[d] = w_fc[u];
        #pragma unroll
        for (int g = 0; g < 4; ++g) {
            int row = g * 512 + u;
            bs[g][d] = b_ih[row] + b_hh[row];
            ws[g][d] = w_ih[row];
        }
    }
    const float bfc = b_fc[0];
    int bth[4][2];
    #pragma unroll
    for (int mt = 0; mt < 4; ++mt)
        #pragma unroll
        for (int hh = 0; hh < 2; ++hh)
            bth[mt][hh] = i * 128 + wm * 64 + mt * 16 + qr + 8 * hh;
    const int kpos = j * 32 + wn * 8 + 2 * ql;   // this thread's k-slot in h_pack

    // ---- resident w: 8 panels of [128 rows][64 k] fp16, SW128 swizzled ----
    for (int idx = tid; idx < 8192; idx += 256) {
        int c = idx >> 10, r = (idx >> 3) & 127, q = idx & 7;
        unsigned dst = sa + (unsigned)(c * 16384 + r * 128 + ((q ^ (r & 7)) * 16));
        const char* src = (const char*)g_wpack +
            ((size_t)(j * 128 + r)) * 1024 + c * 128 + q * 16;
        cpa16(dst, src);
    }
    asm volatile("cp.async.commit_group;\n\tcp.async.wait_group 0;" ::: "memory");
    __syncthreads();

    // staging (cp.async) parameters for A (h fp16), 16KB per chunk, 3-slot ring
    const int sr = tid >> 1, sq = tid & 1;
    const char* pA0 = (const char*)g_hpack + (size_t)(i * 128 + sr) * 1024 + sq * 64;
    const unsigned sdst = sa + OFF_STA + (unsigned)(sr * 128);
    unsigned swo[4];
    #pragma unroll
    for (int qq = 0; qq < 4; ++qq)
        swo[qq] = (unsigned)((((sq * 4 + qq) ^ (sr & 7))) << 4);

    // ldmatrix thread bases
    const int rl = lane & 15, qsel = lane >> 4, sw7 = rl & 7;
    const unsigned thA = (unsigned)((wm * 64 + rl) * 128);
    const unsigned thB = (unsigned)((wn * 32 + rl) * 128);

    float cst[4][4];
    #pragma unroll
    for (int mt = 0; mt < 4; ++mt)
        #pragma unroll
        for (int e = 0; e < 4; ++e) cst[mt][e] = 0.f;

    #define LOADCHUNK(c, s) do {                                              \
        unsigned _db = sdst + (unsigned)((s) * 16384);                         \
        const char* _a0 = pA0 + (c) * 128;                                     \
        _Pragma("unroll")                                                      \
        for (int qq = 0; qq < 4; ++qq)                                         \
            cpa16(_db + swo[qq], _a0 + qq * 16);                               \
        asm volatile("cp.async.commit_group;" ::: "memory");                   \
    } while (0)

    for (int t = 0; t < 560; ++t) {
        // ---- group barrier wait: h(t) and xdec(t) produced by group i ----
        if (t > 0) {
            if (tid == 0) {
                unsigned tgt = (unsigned)(t << 4);   // 16*t arrivals
                unsigned v;
                do {
                    asm volatile("ld.acquire.gpu.global.u32 %0, [%1];"
                                 : "=r"(v) : "l"(cptr) : "memory");
                    if (v < tgt) __nanosleep(32);
                } while (v < tgt);
            }
            __syncthreads();
        }

        // stage chunks 0,1 so they overlap the x loads below
        LOADCHUNK(0, 0);
        LOADCHUNK(1, 1);

        // ---- step input ----
        float xtv[4][2];
        if (t < 512) {
            #pragma unroll
            for (int mt = 0; mt < 4; ++mt)
                #pragma unroll
                for (int hh = 0; hh < 2; ++hh)
                    xtv[mt][hh] = g_xT[t * 1024 + bth[mt][hh]];
        } else {
            int p = t - 512;
            #pragma unroll
            for (int mt = 0; mt < 4; ++mt)
                #pragma unroll
                for (int hh = 0; hh < 2; ++hh) {
                    xtv[mt][hh] = g_xdec[p * 1024 + bth[mt][hh]] + bfc;
                    if (j == 0 && wn == 0 && ql == 0)
                        dout[bth[mt][hh] * 48 + p] = xtv[mt][hh];
                }
            if (t == 559) break;
        }

        float D[4][4][4];
        #pragma unroll
        for (int mt = 0; mt < 4; ++mt)
            #pragma unroll
            for (int nt = 0; nt < 4; ++nt)
                #pragma unroll
                for (int e = 0; e < 4; ++e) D[mt][nt][e] = 0.f;

        // ---- GEMM: 8 chunks, 3-slot ring, fp16-acc HMMA + per-chunk promote
        #pragma unroll 1
        for (int c = 0; c < 8; ++c) {
            if (c < 7)
                asm volatile("cp.async.wait_group 1;" ::: "memory");
            else
                asm volatile("cp.async.wait_group 0;" ::: "memory");
            __syncthreads();
            if (c + 2 < 8) {
                int s2 = c + 2; s2 = (s2 >= 3) ? (s2 >= 6 ? s2 - 6 : s2 - 3) : s2;
                LOADCHUNK(c + 2, s2);
            }
            int sc = (c >= 3) ? (c >= 6 ? c - 6 : c - 3) : c;
            const unsigned stA = sa + OFF_STA + (unsigned)(sc * 16384);
            const unsigned stB = sa + (unsigned)(c * 16384);

            uint32_t Dh[4][4][2];   // fp16 accumulators for this chunk
            #pragma unroll
            for (int mt = 0; mt < 4; ++mt)
                #pragma unroll
                for (int nt = 0; nt < 4; ++nt) {
                    Dh[mt][nt][0] = 0u; Dh[mt][nt][1] = 0u;
                }

            #pragma unroll
            for (int k16 = 0; k16 < 4; ++k16) {
                unsigned swz = (unsigned)((((k16 * 2 + qsel) ^ sw7)) << 4);
                uint32_t Bf[4][2];
                #pragma unroll
                for (int nb = 0; nb < 2; ++nb) {
                    uint32_t r0, r1, r2, r3;
                    ldmx4(r0, r1, r2, r3, stB + thB + nb * 2048 + swz);
                    Bf[2 * nb][0] = r0; Bf[2 * nb][1] = r2;
                    Bf[2 * nb + 1][0] = r1; Bf[2 * nb + 1][1] = r3;
                }
                #pragma unroll
                for (int mt = 0; mt < 4; ++mt) {
                    uint32_t a[4];
                    ldmx4(a[0], a[1], a[2], a[3], stA + thA + mt * 2048 + swz);
                    #pragma unroll
                    for (int nt = 0; nt < 4; ++nt)
                        mma16816h(Dh[mt][nt], a, Bf[nt][0], Bf[nt][1]);
                }
            }

            // promote chunk result to fp32 accumulators
            #pragma unroll
            for (int mt = 0; mt < 4; ++mt)
                #pragma unroll
                for (int nt = 0; nt < 4; ++nt) {
                    float2 f0 = __half22float2(*(__half2*)&Dh[mt][nt][0]);
                    float2 f1 = __half22float2(*(__half2*)&Dh[mt][nt][1]);
                    D[mt][nt][0] += f0.x; D[mt][nt][1] += f0.y;
                    D[mt][nt][2] += f1.x; D[mt][nt][3] += f1.y;
                }
        }

        // ---- epilogue: gates, c/h update, h store, fc ----
        #pragma unroll
        for (int mt = 0; mt < 4; ++mt) {
            #pragma unroll
            for (int hh = 0; hh < 2; ++hh) {
                float xt = xtv[mt][hh];
                float hv2[2];
                #pragma unroll
                for (int d = 0; d < 2; ++d) {
                    int e = hh * 2 + d;
                    float gi = D[mt][0][e] + bs[0][d] + xt * ws[0][d];
                    float gf = D[mt][1][e] + bs[1][d] + xt * ws[1][d];
                    float gg = D[mt][2][e] + bs[2][d] + xt * ws[2][d];
                    float go = D[mt][3][e] + bs[3][d] + xt * ws[3][d];
                    float c2 = sigm(gf) * cst[mt][e] + sigm(gi) * tanha(gg);
                    cst[mt][e] = c2;
                    hv2[d] = sigm(go) * tanha(c2);
                }
                __half h0 = __float2half_rn(hv2[0]);
                __half h1 = __float2half_rn(hv2[1]);
                uint32_t hiu = (uint32_t)__half_as_ushort(h0) |
                               ((uint32_t)__half_as_ushort(h1) << 16);
                size_t off = (size_t)bth[mt][hh] * 1024 + (size_t)kpos * 2;
                *(uint32_t*)((char*)g_hpack + off) = hiu;

                if (t >= 511) {
                    float pa = hv2[0] * wfc_r[0] + hv2[1] * wfc_r[1];
                    pa += __shfl_xor_sync(0xFFFFFFFFu, pa, 1);
                    pa += __shfl_xor_sync(0xFFFFFFFFu, pa, 2);
                    if (ql == 0)
                        atomicAdd(&g_xdec[(t - 511) * 1024 + bth[mt][hh]], pa);
                }
            }
        }

        // ---- group barrier arrive (release: orders h stores + xdec adds) ----
        __syncthreads();
        if (tid == 0)
            asm volatile("red.release.gpu.global.add.u32 [%0], 1;"
                         :: "l"(cptr) : "memory");
    }
    #undef LOADCHUNK
}

extern "C" void kernel_launch(void* const* d_in, const int* in_sizes, int n_in,
                              void* d_out, int out_size) {
    (void)in_sizes; (void)n_in; (void)out_size;
    cudaFuncSetAttribute(lstm_mma, cudaFuncAttributeMaxDynamicSharedMemorySize,
                         SMEM_MAIN);
    prep_k<<<2048, 256>>>((const float*)d_in[0]);
    pack_w<<<4096, 256>>>((const float*)d_in[2]);
    lstm_mma<<<NCTA, 256, SMEM_MAIN>>>(
        (const float*)d_in[1],   // w_ih
        (const float*)d_in[3],   // b_ih
        (const float*)d_in[4],   // b_hh
        (const float*)d_in[5],   // w_fc
        (const float*)d_in[6],   // b_fc
        (float*)d_out);
}